// round 13
// baseline (speedup 1.0000x reference)
#include <cuda_runtime.h>
#include <math.h>

#define BB  64
#define AA  16
#define CC  512
#define HH  30
#define WW  40
#define HWW 1200
#define EE  256
#define PP  512

#define OFF_Z  0
#define OFF_MU 76864
#define OFF_S2 76928
#define OFF_AX 76992
#define OFF_X  153792

#define NZ 10

typedef unsigned long long ull;

#define FMA_F32X2(d, a, b, c) \
    asm("fma.rn.f32x2 %0, %1, %2, %3;" : "=l"(d) : "l"(a), "l"(b), "l"(c))
#define PACK_DUP_F32X2(out, v) \
    asm("mov.b64 %0, {%1, %1};" : "=l"(out) : "f"(v))
#define UNPACK_F32X2(lo, hi, in) \
    asm("mov.b64 {%0, %1}, %2;" : "=f"(lo), "=f"(hi) : "l"(in))

// scratch: every element written each launch before being read (no zeroing needed)
__device__ float g_mean[BB * CC];
__device__ float g_y[BB * AA];
__device__ float g_t1p[8][BB * 48];
__device__ float g_scorep[8][BB * AA];
__device__ float g_aggrp[NZ][BB * AA * CC];
__device__ float g_aggr[BB * AA * CC];

// stream + events created once at library load (host-side resources only)
static cudaStream_t g_s1;
static cudaEvent_t g_evFork, g_evJoin;
namespace {
struct InitStreams {
    InitStreams() {
        cudaStreamCreateWithFlags(&g_s1, cudaStreamNonBlocking);
        cudaEventCreateWithFlags(&g_evFork, cudaEventDisableTiming);
        cudaEventCreateWithFlags(&g_evJoin, cudaEventDisableTiming);
    }
};
InitStreams g_initStreams;
}

// ---------------------------------------------------------------------------
// x[b,a,hw] = relu(w_sal3[a,:] . F[b,:,hw] + b_sal3[a])
// grid (64, 10), block 128.  f32x2 packed accumulators; deep unroll for MLP.
__global__ void __launch_bounds__(128) k_x(const float* __restrict__ F,
                                           const float* __restrict__ w3,
                                           const float* __restrict__ b3,
                                           float* __restrict__ out) {
    __shared__ float ws[CC * AA];  // transposed [c][a] -> natural a-pairs
    int b = blockIdx.x, tid = threadIdx.x;
    for (int i = tid; i < CC * AA; i += 128)
        ws[i] = w3[(i & 15) * CC + (i >> 4)];
    __syncthreads();

    int hw = blockIdx.y * 128 + tid;
    bool v = hw < HWW;
    int hwl = v ? hw : 0;
    const float* Fb = F + (size_t)b * CC * HWW + hwl;

    ull acc[8];
    #pragma unroll
    for (int j = 0; j < 8; j++) acc[j] = 0ULL;

    #pragma unroll 16
    for (int c = 0; c < CC; c++) {
        float f = Fb[c * HWW];
        ull f2; PACK_DUP_F32X2(f2, f);
        const ulonglong2* wp = (const ulonglong2*)(ws + c * 16);
        ulonglong2 wA = wp[0];
        ulonglong2 wB = wp[1];
        ulonglong2 wC = wp[2];
        ulonglong2 wD = wp[3];
        FMA_F32X2(acc[0], f2, wA.x, acc[0]);
        FMA_F32X2(acc[1], f2, wA.y, acc[1]);
        FMA_F32X2(acc[2], f2, wB.x, acc[2]);
        FMA_F32X2(acc[3], f2, wB.y, acc[3]);
        FMA_F32X2(acc[4], f2, wC.x, acc[4]);
        FMA_F32X2(acc[5], f2, wC.y, acc[5]);
        FMA_F32X2(acc[6], f2, wD.x, acc[6]);
        FMA_F32X2(acc[7], f2, wD.y, acc[7]);
    }

    if (v) {
        float* X = out + OFF_X + (size_t)b * AA * HWW + hw;
        #pragma unroll
        for (int j = 0; j < 8; j++) {
            float lo, hi;
            UNPACK_F32X2(lo, hi, acc[j]);
            X[(2 * j + 0) * HWW] = fmaxf(lo + b3[2 * j + 0], 0.f);
            X[(2 * j + 1) * HWW] = fmaxf(hi + b3[2 * j + 1], 0.f);
        }
    }
}

// ---------------------------------------------------------------------------
// Fused drt1 conv partials + per-channel mean of F.
// grid (64, 4), block 384; yoff selects half of the 8 channel-chunks.
__global__ void __launch_bounds__(384) k_drt1f(const float* __restrict__ F,
                                               const float* __restrict__ w1,
                                               int yoff) {
    __shared__ float ch[2][HWW];
    __shared__ float wsh[64 * 49];
    __shared__ float csum[2][12];
    __shared__ float pos_acc[336];

    int chunkid = blockIdx.y + yoff;
    int b = blockIdx.x, c0 = chunkid * 64;
    int tid = threadIdx.x;
    int wid = tid >> 5, lane = tid & 31;

    for (int i = tid; i < 64 * 49; i += 384) wsh[i] = w1[c0 * 49 + i];

    int pos = tid / 7, kh = tid - pos * 7;
    bool active = tid < 336;
    int oh = pos >> 3, ow = pos & 7;
    int ih = oh * 5 - 2 + kh;
    int iw0 = ow * 5 - 2;
    bool ihok = active && ih >= 0;

    const float* Fb = F + ((size_t)b * CC + c0) * HWW;

    {
        float ps = 0.f;
        if (tid < 300) {
            float4 v = ((const float4*)Fb)[tid];
            ((float4*)ch[0])[tid] = v;
            ps = v.x + v.y + v.z + v.w;
        }
        #pragma unroll
        for (int o = 16; o; o >>= 1) ps += __shfl_xor_sync(0xFFFFFFFFu, ps, o);
        if (!lane) csum[0][wid] = ps;
    }
    __syncthreads();

    float acc = 0.f;
    for (int c = 0; c < 64; c++) {
        int cur = c & 1;
        if (c < 63) {
            float ps = 0.f;
            if (tid < 300) {
                float4 v = ((const float4*)(Fb + (size_t)(c + 1) * HWW))[tid];
                ((float4*)ch[cur ^ 1])[tid] = v;
                ps = v.x + v.y + v.z + v.w;
            }
            #pragma unroll
            for (int o = 16; o; o >>= 1) ps += __shfl_xor_sync(0xFFFFFFFFu, ps, o);
            if (!lane) csum[cur ^ 1][wid] = ps;
        }
        if (tid == 0) {
            float m = 0.f;
            #pragma unroll
            for (int w = 0; w < 12; w++) m += csum[cur][w];
            g_mean[b * CC + c0 + c] = m * (1.f / HWW);
        }
        if (ihok) {
            const float* row = ch[cur] + ih * WW;
            const float* wr = wsh + c * 49 + kh * 7;
            #pragma unroll
            for (int kw = 0; kw < 7; kw++) {
                int iw = iw0 + kw;
                if (iw >= 0) acc += row[iw] * wr[kw];
            }
        }
        __syncthreads();
    }

    if (active) pos_acc[tid] = acc;
    __syncthreads();
    if (active && kh == 0) {
        float s = pos_acc[tid] + pos_acc[tid + 1] + pos_acc[tid + 2]
                + pos_acc[tid + 3] + pos_acc[tid + 4] + pos_acc[tid + 5]
                + pos_acc[tid + 6];
        g_t1p[chunkid][b * 48 + pos] = s;
    }
}

// ---------------------------------------------------------------------------
// merged y + drt2.  grid 64, block 512
__global__ void __launch_bounds__(512) k_ydrt2(
    const float* __restrict__ w2, const float* __restrict__ b2,
    const float* __restrict__ wd2, const float* __restrict__ bd2,
    const float* __restrict__ bd1, float* __restrict__ out) {
    __shared__ float t1s[48];
    int b = blockIdx.x, tid = threadIdx.x;
    int a = tid >> 5, lane = tid & 31;

    if (tid < 48) {
        float t = 0.f;
        #pragma unroll
        for (int j = 0; j < 8; j++) t += g_t1p[j][b * 48 + tid];
        t1s[tid] = fmaxf(t + bd1[0], 0.f);
    }

    const float4* m4 = (const float4*)(g_mean + b * CC);
    const float4* w4 = (const float4*)(w2 + a * CC);
    float s = 0.f;
    #pragma unroll
    for (int i = 0; i < 4; i++) {
        float4 mv = m4[lane + 32 * i];
        float4 wv = w4[lane + 32 * i];
        s += mv.x * wv.x + mv.y * wv.y + mv.z * wv.z + mv.w * wv.w;
    }
    #pragma unroll
    for (int o = 16; o; o >>= 1) s += __shfl_xor_sync(0xFFFFFFFFu, s, o);
    if (!lane) g_y[b * AA + a] = s + b2[a];

    __syncthreads();
    if (tid < 64) {
        int o = tid >> 5;
        float s2 = 0.f;
        for (int i = lane; i < 48; i += 32) s2 += t1s[i] * wd2[o * 48 + i];
        #pragma unroll
        for (int sh = 16; sh; sh >>= 1) s2 += __shfl_xor_sync(0xFFFFFFFFu, s2, sh);
        if (!lane) {
            float v = s2 + bd2[o];
            if (o == 0) out[OFF_MU + b] = v;
            else        out[OFF_S2 + b] = expf(v);
        }
    }
}

// ---------------------------------------------------------------------------
// aggr partial v3 (scalar): grid (64, NZ), block 256.
#define ACH 20
__global__ void __launch_bounds__(256) k_aggr(const float* __restrict__ Eenc,
                                              const float* __restrict__ out) {
    __shared__ float Esh[ACH * 512];     // [k][c]
    __shared__ float Xsh[ACH * 16];      // [k][a]
    int b = blockIdx.x;
    int z = blockIdx.y;
    int tid = threadIdx.x;
    int tc = tid & 63;
    int ta = tid >> 6;

    const float* Eb = Eenc + (size_t)b * CC * HWW;
    const float* Xb = out + OFF_X + (size_t)b * AA * HWW;

    float acc[4][8];
    #pragma unroll
    for (int i = 0; i < 4; i++)
        #pragma unroll
        for (int j = 0; j < 8; j++) acc[i][j] = 0.f;

    int hwbase = z * 120;
    for (int chk = 0; chk < 6; chk++) {
        int k0 = hwbase + chk * ACH;
        #pragma unroll
        for (int r = 0; r < 2; r++) {
            int c = tid + r * 256;
            const float4* Er = (const float4*)(Eb + (size_t)c * HWW + k0);
            #pragma unroll
            for (int q = 0; q < 5; q++) {
                float4 v = Er[q];
                Esh[(q * 4 + 0) * 512 + c] = v.x;
                Esh[(q * 4 + 1) * 512 + c] = v.y;
                Esh[(q * 4 + 2) * 512 + c] = v.z;
                Esh[(q * 4 + 3) * 512 + c] = v.w;
            }
        }
        if (tid < 80) {
            int aa = tid / 5, q = tid % 5;
            float4 v = *(const float4*)(Xb + aa * HWW + k0 + q * 4);
            Xsh[(q * 4 + 0) * 16 + aa] = v.x;
            Xsh[(q * 4 + 1) * 16 + aa] = v.y;
            Xsh[(q * 4 + 2) * 16 + aa] = v.z;
            Xsh[(q * 4 + 3) * 16 + aa] = v.w;
        }
        __syncthreads();
        #pragma unroll
        for (int k = 0; k < ACH; k++) {
            float4 e0 = *(const float4*)(Esh + k * 512 + tc * 4);
            float4 e1 = *(const float4*)(Esh + k * 512 + 256 + tc * 4);
            float4 xv = *(const float4*)(Xsh + k * 16 + ta * 4);
            float ev[8] = {e0.x, e0.y, e0.z, e0.w, e1.x, e1.y, e1.z, e1.w};
            float xa[4] = {xv.x, xv.y, xv.z, xv.w};
            #pragma unroll
            for (int i = 0; i < 4; i++)
                #pragma unroll
                for (int j = 0; j < 8; j++)
                    acc[i][j] += xa[i] * ev[j];
        }
        __syncthreads();
    }

    float* dst = g_aggrp[z] + (size_t)b * AA * CC;
    #pragma unroll
    for (int i = 0; i < 4; i++) {
        int a = ta * 4 + i;
        float4 s0, s1;
        s0.x = acc[i][0] * (1.f / HWW); s0.y = acc[i][1] * (1.f / HWW);
        s0.z = acc[i][2] * (1.f / HWW); s0.w = acc[i][3] * (1.f / HWW);
        s1.x = acc[i][4] * (1.f / HWW); s1.y = acc[i][5] * (1.f / HWW);
        s1.z = acc[i][6] * (1.f / HWW); s1.w = acc[i][7] * (1.f / HWW);
        *(float4*)(dst + a * CC + tc * 4) = s0;
        *(float4*)(dst + a * CC + 256 + tc * 4) = s1;
    }
}

// ---------------------------------------------------------------------------
// reduce NZ aggr partials -> g_aggr.  grid 512, block 256, float4 per thread.
__global__ void __launch_bounds__(256) k_sumaggr() {
    int i4 = blockIdx.x * 256 + threadIdx.x;     // 131072 float4s
    float4 s = ((const float4*)g_aggrp[0])[i4];
    #pragma unroll
    for (int z = 1; z < NZ; z++) {
        float4 v = ((const float4*)g_aggrp[z])[i4];
        s.x += v.x; s.y += v.y; s.z += v.z; s.w += v.w;
    }
    ((float4*)g_aggr)[i4] = s;
}

// ---------------------------------------------------------------------------
// attention scores v2 — register-tiled GEMM.
// grid (64, 8): (b, 64-p chunk).  block 256 = 16 pg x 4 ag x 4 kg.
#define AGPAD 514
#define SKPAD 69
__global__ void __launch_bounds__(256) k_score(
    const float* __restrict__ subj, const float* __restrict__ wps,
    const float* __restrict__ bps, const float* __restrict__ wpf,
    const float* __restrict__ bpf, const float* __restrict__ watt) {
    __shared__ float ssub[EE];
    __shared__ float psall[64];          // proj_s + bps + bpf
    __shared__ float wattS[64];
    __shared__ float aggs[AA * AGPAD];   // [a][c], row stride 514
    __shared__ float ubuf[64 * SKPAD];   // wpfS [p][k] chunk; later aliased for k-reduce
    __shared__ float scw[16][16];        // [pg][a]

    int b = blockIdx.x, p0 = blockIdx.y * 64;
    int tid = threadIdx.x;
    int wid = tid >> 5, lane = tid & 31;
    int pg = tid & 15, ag = (tid >> 4) & 3, kg = tid >> 6;

    for (int i = tid; i < EE; i += 256) ssub[i] = subj[b * EE + i];
    if (tid < 64) wattS[tid] = watt[p0 + tid];

    {
        const float4* src = (const float4*)(g_aggr + (size_t)b * AA * CC);
        for (int i4 = tid; i4 < AA * CC / 4; i4 += 256) {
            int a = i4 >> 7, c4 = i4 & 127;
            float4 v = src[i4];
            float* d = aggs + a * AGPAD + c4 * 4;
            d[0] = v.x; d[1] = v.y; d[2] = v.z; d[3] = v.w;
        }
    }
    __syncthreads();

    for (int pi = wid; pi < 64; pi += 8) {
        int p = p0 + pi;
        const float4* w4 = (const float4*)(wps + p * EE);
        const float4* s4 = (const float4*)ssub;
        float s = 0.f;
        #pragma unroll
        for (int i = 0; i < 2; i++) {
            float4 wv = w4[lane + 32 * i], sv = s4[lane + 32 * i];
            s += wv.x * sv.x + wv.y * sv.y + wv.z * sv.z + wv.w * sv.w;
        }
        #pragma unroll
        for (int o = 16; o; o >>= 1) s += __shfl_xor_sync(0xFFFFFFFFu, s, o);
        if (!lane) psall[pi] = s + bps[p] + bpf[p];
    }

    float acc[4][4];   // [i: a][j: p]
    #pragma unroll
    for (int i = 0; i < 4; i++)
        #pragma unroll
        for (int j = 0; j < 4; j++) acc[i][j] = 0.f;

    for (int cc = 0; cc < 8; cc++) {
        int c0 = cc * 64;
        __syncthreads();
        for (int i4 = tid; i4 < 1024; i4 += 256) {
            int p = i4 >> 4, q = i4 & 15;
            float4 v = *(const float4*)(wpf + (size_t)(p0 + p) * CC + c0 + q * 4);
            float* d = ubuf + p * SKPAD + q * 4;
            d[0] = v.x; d[1] = v.y; d[2] = v.z; d[3] = v.w;
        }
        __syncthreads();
        #pragma unroll
        for (int kk = 0; kk < 16; kk++) {
            int k = kg * 16 + kk;
            float wv[4], av[4];
            #pragma unroll
            for (int j = 0; j < 4; j++)
                wv[j] = ubuf[(pg + 16 * j) * SKPAD + k];
            #pragma unroll
            for (int i = 0; i < 4; i++)
                av[i] = aggs[(ag * 4 + i) * AGPAD + c0 + k];
            #pragma unroll
            for (int i = 0; i < 4; i++)
                #pragma unroll
                for (int j = 0; j < 4; j++)
                    acc[i][j] += av[i] * wv[j];
        }
    }
    __syncthreads();

    int tt = pg + 16 * ag;
    {
        float* d = ubuf + (kg * 64 + tt) * 17;
        #pragma unroll
        for (int i = 0; i < 4; i++)
            #pragma unroll
            for (int j = 0; j < 4; j++)
                d[i * 4 + j] = acc[i][j];
    }
    __syncthreads();

    if (kg == 0) {
        float contrib[4] = {0.f, 0.f, 0.f, 0.f};
        #pragma unroll
        for (int j = 0; j < 4; j++) {
            int pl = pg + 16 * j;
            float wt = wattS[pl], pb = psall[pl];
            #pragma unroll
            for (int i = 0; i < 4; i++) {
                float dot = 0.f;
                #pragma unroll
                for (int g = 0; g < 4; g++)
                    dot += ubuf[(g * 64 + tt) * 17 + i * 4 + j];
                contrib[i] += wt * tanhf(dot + pb);
            }
        }
        #pragma unroll
        for (int i = 0; i < 4; i++)
            scw[pg][ag * 4 + i] = contrib[i];
    }
    __syncthreads();
    if (tid < 16) {
        float v = 0.f;
        #pragma unroll
        for (int g = 0; g < 16; g++) v += scw[g][tid];
        g_scorep[blockIdx.y][b * 16 + tid] = v;
    }
}

// ---------------------------------------------------------------------------
// softmax (redundant per block) + weighted sums.  grid (64,5), block 256
__global__ void k_final(float* __restrict__ out) {
    __shared__ float sc[16];
    __shared__ float aw[16];
    int b = blockIdx.x, tid = threadIdx.x;
    if (tid < 16) {
        float v = 0.f;
        #pragma unroll
        for (int j = 0; j < 8; j++) v += g_scorep[j][b * 16 + tid];
        sc[tid] = v;
    }
    __syncthreads();
    if (tid < 16) {
        float m = -1e30f;
        #pragma unroll
        for (int i = 0; i < 16; i++) m = fmaxf(m, sc[i]);
        float sum = 0.f;
        #pragma unroll
        for (int i = 0; i < 16; i++) sum += expf(sc[i] - m);
        aw[tid] = expf(sc[tid] - m) / sum;
    }
    __syncthreads();

    int hw = blockIdx.y * 256 + tid;
    if (hw < HWW) {
        const float* X = out + OFF_X + (size_t)b * AA * HWW;
        float s = 0.f;
        #pragma unroll
        for (int a = 0; a < 16; a++) s += X[a * HWW + hw] * aw[a];
        out[OFF_AX + b * HWW + hw] = s;
        out[OFF_Z + b * 1201 + 1 + hw] = s;
    }
    if (tid == 0 && blockIdx.y == 0) {
        float z = 0.f;
        #pragma unroll
        for (int a = 0; a < 16; a++) z += g_y[b * 16 + a] * aw[a];
        out[OFF_Z + b * 1201] = z;
    }
}

// ---------------------------------------------------------------------------
extern "C" void kernel_launch(void* const* d_in, const int* in_sizes, int n_in,
                              void* d_out, int out_size) {
    const float* enc  = (const float*)d_in[0];
    const float* feat = (const float*)d_in[1];
    const float* subj = (const float*)d_in[2];
    const float* w2   = (const float*)d_in[3];
    const float* b2   = (const float*)d_in[4];
    const float* w3   = (const float*)d_in[5];
    const float* b3   = (const float*)d_in[6];
    const float* wd1  = (const float*)d_in[7];
    const float* bd1  = (const float*)d_in[8];
    const float* wd2  = (const float*)d_in[9];
    const float* bd2  = (const float*)d_in[10];
    const float* wpf  = (const float*)d_in[11];
    const float* bpf  = (const float*)d_in[12];
    const float* wps  = (const float*)d_in[13];
    const float* bps  = (const float*)d_in[14];
    const float* watt = (const float*)d_in[15];
    float* out = (float*)d_out;

    cudaEventRecord(g_evFork, 0);
    cudaStreamWaitEvent(g_s1, g_evFork, 0);

    k_drt1f<<<dim3(64, 4), 384, 0, g_s1>>>(feat, wd1, 0);          // 1 (s1)
    k_drt1f<<<dim3(64, 4), 384, 0, g_s1>>>(feat, wd1, 4);          // 2 (s1)
    k_ydrt2<<<64, 512, 0, g_s1>>>(w2, b2, wd2, bd2, bd1, out);     // 3 (s1)
    k_x<<<dim3(64, 10), 128>>>(feat, w3, b3, out);                 // 4 (s0) <- profiled
    k_aggr<<<dim3(64, NZ), 256>>>(enc, out);                       // 5 (s0)
    k_sumaggr<<<512, 256>>>();                                     // 6 (s0)
    k_score<<<dim3(64, 8), 256>>>(subj, wps, bps, wpf, bpf, watt); // 7 (s0)

    cudaEventRecord(g_evJoin, g_s1);
    cudaStreamWaitEvent(0, g_evJoin, 0);
    k_final<<<dim3(64, 5), 256>>>(out);                            // 8 (s0)
}

// round 14
// speedup vs baseline: 1.4296x; 1.4296x over previous
#include <cuda_runtime.h>
#include <math.h>

#define BB  64
#define AA  16
#define CC  512
#define HH  30
#define WW  40
#define HWW 1200
#define EE  256
#define PP  512

#define OFF_Z  0
#define OFF_MU 76864
#define OFF_S2 76928
#define OFF_AX 76992
#define OFF_X  153792

#define NZ 15

typedef unsigned long long ull;

#define FMA_F32X2(d, a, b, c) \
    asm("fma.rn.f32x2 %0, %1, %2, %3;" : "=l"(d) : "l"(a), "l"(b), "l"(c))
#define PACK_DUP_F32X2(out, v) \
    asm("mov.b64 %0, {%1, %1};" : "=l"(out) : "f"(v))
#define UNPACK_F32X2(lo, hi, in) \
    asm("mov.b64 {%0, %1}, %2;" : "=f"(lo), "=f"(hi) : "l"(in))

// scratch: every element written each launch before being read (no zeroing needed)
__device__ float g_mean[BB * CC];
__device__ float g_y[BB * AA];
__device__ float g_t1p[8][BB * 48];
__device__ float g_scorep[8][BB * AA];
__device__ float g_aggrp[NZ][BB * AA * CC];
__device__ float g_aggr[BB * AA * CC];

// stream + events created once at library load (host-side resources only)
static cudaStream_t g_s1;
static cudaEvent_t g_evFork, g_evJoin;
namespace {
struct InitStreams {
    InitStreams() {
        cudaStreamCreateWithFlags(&g_s1, cudaStreamNonBlocking);
        cudaEventCreateWithFlags(&g_evFork, cudaEventDisableTiming);
        cudaEventCreateWithFlags(&g_evJoin, cudaEventDisableTiming);
    }
};
InitStreams g_initStreams;
}

// ---------------------------------------------------------------------------
// x[b,a,hw] = relu(w_sal3[a,:] . F[b,:,hw] + b_sal3[a])
// grid (64, 10), block 128.  f32x2 packed accumulators over a-pairs. (R6/R12 best)
__global__ void __launch_bounds__(128) k_x(const float* __restrict__ F,
                                           const float* __restrict__ w3,
                                           const float* __restrict__ b3,
                                           float* __restrict__ out) {
    __shared__ float ws[CC * AA];  // transposed [c][a] -> natural a-pairs
    int b = blockIdx.x, tid = threadIdx.x;
    for (int i = tid; i < CC * AA; i += 128)
        ws[i] = w3[(i & 15) * CC + (i >> 4)];
    __syncthreads();

    int hw = blockIdx.y * 128 + tid;
    bool v = hw < HWW;
    int hwl = v ? hw : 0;
    const float* Fb = F + (size_t)b * CC * HWW + hwl;

    ull acc[8];
    #pragma unroll
    for (int j = 0; j < 8; j++) acc[j] = 0ULL;

    #pragma unroll 4
    for (int c = 0; c < CC; c++) {
        float f = Fb[c * HWW];
        ull f2; PACK_DUP_F32X2(f2, f);
        const ulonglong2* wp = (const ulonglong2*)(ws + c * 16);
        ulonglong2 wA = wp[0];
        ulonglong2 wB = wp[1];
        ulonglong2 wC = wp[2];
        ulonglong2 wD = wp[3];
        FMA_F32X2(acc[0], f2, wA.x, acc[0]);
        FMA_F32X2(acc[1], f2, wA.y, acc[1]);
        FMA_F32X2(acc[2], f2, wB.x, acc[2]);
        FMA_F32X2(acc[3], f2, wB.y, acc[3]);
        FMA_F32X2(acc[4], f2, wC.x, acc[4]);
        FMA_F32X2(acc[5], f2, wC.y, acc[5]);
        FMA_F32X2(acc[6], f2, wD.x, acc[6]);
        FMA_F32X2(acc[7], f2, wD.y, acc[7]);
    }

    if (v) {
        float* X = out + OFF_X + (size_t)b * AA * HWW + hw;
        #pragma unroll
        for (int j = 0; j < 8; j++) {
            float lo, hi;
            UNPACK_F32X2(lo, hi, acc[j]);
            X[(2 * j + 0) * HWW] = fmaxf(lo + b3[2 * j + 0], 0.f);
            X[(2 * j + 1) * HWW] = fmaxf(hi + b3[2 * j + 1], 0.f);
        }
    }
}

// ---------------------------------------------------------------------------
// Fused drt1 conv partials + per-channel mean of F.  grid (64, 8), block 384
__global__ void __launch_bounds__(384) k_drt1f(const float* __restrict__ F,
                                               const float* __restrict__ w1) {
    __shared__ float ch[2][HWW];
    __shared__ float wsh[64 * 49];
    __shared__ float csum[2][12];
    __shared__ float pos_acc[336];

    int chunkid = blockIdx.y;
    int b = blockIdx.x, c0 = chunkid * 64;
    int tid = threadIdx.x;
    int wid = tid >> 5, lane = tid & 31;

    for (int i = tid; i < 64 * 49; i += 384) wsh[i] = w1[c0 * 49 + i];

    int pos = tid / 7, kh = tid - pos * 7;
    bool active = tid < 336;
    int oh = pos >> 3, ow = pos & 7;
    int ih = oh * 5 - 2 + kh;
    int iw0 = ow * 5 - 2;
    bool ihok = active && ih >= 0;

    const float* Fb = F + ((size_t)b * CC + c0) * HWW;

    {
        float ps = 0.f;
        if (tid < 300) {
            float4 v = ((const float4*)Fb)[tid];
            ((float4*)ch[0])[tid] = v;
            ps = v.x + v.y + v.z + v.w;
        }
        #pragma unroll
        for (int o = 16; o; o >>= 1) ps += __shfl_xor_sync(0xFFFFFFFFu, ps, o);
        if (!lane) csum[0][wid] = ps;
    }
    __syncthreads();

    float acc = 0.f;
    for (int c = 0; c < 64; c++) {
        int cur = c & 1;
        if (c < 63) {
            float ps = 0.f;
            if (tid < 300) {
                float4 v = ((const float4*)(Fb + (size_t)(c + 1) * HWW))[tid];
                ((float4*)ch[cur ^ 1])[tid] = v;
                ps = v.x + v.y + v.z + v.w;
            }
            #pragma unroll
            for (int o = 16; o; o >>= 1) ps += __shfl_xor_sync(0xFFFFFFFFu, ps, o);
            if (!lane) csum[cur ^ 1][wid] = ps;
        }
        if (tid == 0) {
            float m = 0.f;
            #pragma unroll
            for (int w = 0; w < 12; w++) m += csum[cur][w];
            g_mean[b * CC + c0 + c] = m * (1.f / HWW);
        }
        if (ihok) {
            const float* row = ch[cur] + ih * WW;
            const float* wr = wsh + c * 49 + kh * 7;
            #pragma unroll
            for (int kw = 0; kw < 7; kw++) {
                int iw = iw0 + kw;
                if (iw >= 0) acc += row[iw] * wr[kw];
            }
        }
        __syncthreads();
    }

    if (active) pos_acc[tid] = acc;
    __syncthreads();
    if (active && kh == 0) {
        float s = pos_acc[tid] + pos_acc[tid + 1] + pos_acc[tid + 2]
                + pos_acc[tid + 3] + pos_acc[tid + 4] + pos_acc[tid + 5]
                + pos_acc[tid + 6];
        g_t1p[chunkid][b * 48 + pos] = s;
    }
}

// ---------------------------------------------------------------------------
// merged y + drt2.  grid 64, block 512
__global__ void __launch_bounds__(512) k_ydrt2(
    const float* __restrict__ w2, const float* __restrict__ b2,
    const float* __restrict__ wd2, const float* __restrict__ bd2,
    const float* __restrict__ bd1, float* __restrict__ out) {
    __shared__ float t1s[48];
    int b = blockIdx.x, tid = threadIdx.x;
    int a = tid >> 5, lane = tid & 31;

    if (tid < 48) {
        float t = 0.f;
        #pragma unroll
        for (int j = 0; j < 8; j++) t += g_t1p[j][b * 48 + tid];
        t1s[tid] = fmaxf(t + bd1[0], 0.f);
    }

    const float4* m4 = (const float4*)(g_mean + b * CC);
    const float4* w4 = (const float4*)(w2 + a * CC);
    float s = 0.f;
    #pragma unroll
    for (int i = 0; i < 4; i++) {
        float4 mv = m4[lane + 32 * i];
        float4 wv = w4[lane + 32 * i];
        s += mv.x * wv.x + mv.y * wv.y + mv.z * wv.z + mv.w * wv.w;
    }
    #pragma unroll
    for (int o = 16; o; o >>= 1) s += __shfl_xor_sync(0xFFFFFFFFu, s, o);
    if (!lane) g_y[b * AA + a] = s + b2[a];

    __syncthreads();
    if (tid < 64) {
        int o = tid >> 5;
        float s2 = 0.f;
        for (int i = lane; i < 48; i += 32) s2 += t1s[i] * wd2[o * 48 + i];
        #pragma unroll
        for (int sh = 16; sh; sh >>= 1) s2 += __shfl_xor_sync(0xFFFFFFFFu, s2, sh);
        if (!lane) {
            float v = s2 + bd2[o];
            if (o == 0) out[OFF_MU + b] = v;
            else        out[OFF_S2 + b] = expf(v);
        }
    }
}

// ---------------------------------------------------------------------------
// aggr partial v3: grid (64, NZ), block 256.  hw slice 80, 4 chunks of ACH=20.
#define ACH 20
__global__ void __launch_bounds__(256) k_aggr(const float* __restrict__ Eenc,
                                              const float* __restrict__ out) {
    __shared__ float Esh[ACH * 512];     // [k][c]
    __shared__ float Xsh[ACH * 16];      // [k][a]
    int b = blockIdx.x;
    int z = blockIdx.y;
    int tid = threadIdx.x;
    int tc = tid & 63;
    int ta = tid >> 6;

    const float* Eb = Eenc + (size_t)b * CC * HWW;
    const float* Xb = out + OFF_X + (size_t)b * AA * HWW;

    float acc[4][8];
    #pragma unroll
    for (int i = 0; i < 4; i++)
        #pragma unroll
        for (int j = 0; j < 8; j++) acc[i][j] = 0.f;

    int hwbase = z * 80;
    for (int chk = 0; chk < 4; chk++) {
        int k0 = hwbase + chk * ACH;
        #pragma unroll
        for (int r = 0; r < 2; r++) {
            int c = tid + r * 256;
            const float4* Er = (const float4*)(Eb + (size_t)c * HWW + k0);
            #pragma unroll
            for (int q = 0; q < 5; q++) {
                float4 v = Er[q];
                Esh[(q * 4 + 0) * 512 + c] = v.x;
                Esh[(q * 4 + 1) * 512 + c] = v.y;
                Esh[(q * 4 + 2) * 512 + c] = v.z;
                Esh[(q * 4 + 3) * 512 + c] = v.w;
            }
        }
        if (tid < 80) {
            int aa = tid / 5, q = tid % 5;
            float4 v = *(const float4*)(Xb + aa * HWW + k0 + q * 4);
            Xsh[(q * 4 + 0) * 16 + aa] = v.x;
            Xsh[(q * 4 + 1) * 16 + aa] = v.y;
            Xsh[(q * 4 + 2) * 16 + aa] = v.z;
            Xsh[(q * 4 + 3) * 16 + aa] = v.w;
        }
        __syncthreads();
        #pragma unroll
        for (int k = 0; k < ACH; k++) {
            float4 e0 = *(const float4*)(Esh + k * 512 + tc * 4);
            float4 e1 = *(const float4*)(Esh + k * 512 + 256 + tc * 4);
            float4 xv = *(const float4*)(Xsh + k * 16 + ta * 4);
            float ev[8] = {e0.x, e0.y, e0.z, e0.w, e1.x, e1.y, e1.z, e1.w};
            float xa[4] = {xv.x, xv.y, xv.z, xv.w};
            #pragma unroll
            for (int i = 0; i < 4; i++)
                #pragma unroll
                for (int j = 0; j < 8; j++)
                    acc[i][j] += xa[i] * ev[j];
        }
        __syncthreads();
    }

    float* dst = g_aggrp[z] + (size_t)b * AA * CC;
    #pragma unroll
    for (int i = 0; i < 4; i++) {
        int a = ta * 4 + i;
        float4 s0, s1;
        s0.x = acc[i][0] * (1.f / HWW); s0.y = acc[i][1] * (1.f / HWW);
        s0.z = acc[i][2] * (1.f / HWW); s0.w = acc[i][3] * (1.f / HWW);
        s1.x = acc[i][4] * (1.f / HWW); s1.y = acc[i][5] * (1.f / HWW);
        s1.z = acc[i][6] * (1.f / HWW); s1.w = acc[i][7] * (1.f / HWW);
        *(float4*)(dst + a * CC + tc * 4) = s0;
        *(float4*)(dst + a * CC + 256 + tc * 4) = s1;
    }
}

// ---------------------------------------------------------------------------
// reduce NZ aggr partials -> g_aggr.  grid 512, block 256, float4 per thread.
__global__ void __launch_bounds__(256) k_sumaggr() {
    int i4 = blockIdx.x * 256 + threadIdx.x;     // 131072 float4s
    float4 s = ((const float4*)g_aggrp[0])[i4];
    #pragma unroll
    for (int z = 1; z < NZ; z++) {
        float4 v = ((const float4*)g_aggrp[z])[i4];
        s.x += v.x; s.y += v.y; s.z += v.z; s.w += v.w;
    }
    ((float4*)g_aggr)[i4] = s;
}

// ---------------------------------------------------------------------------
// attention scores v2 — register-tiled GEMM.
// grid (64, 8): (b, 64-p chunk).  block 256 = 16 pg x 4 ag x 4 kg.
#define AGPAD 514
#define SKPAD 69
__global__ void __launch_bounds__(256) k_score(
    const float* __restrict__ subj, const float* __restrict__ wps,
    const float* __restrict__ bps, const float* __restrict__ wpf,
    const float* __restrict__ bpf, const float* __restrict__ watt) {
    __shared__ float ssub[EE];
    __shared__ float psall[64];          // proj_s + bps + bpf
    __shared__ float wattS[64];
    __shared__ float aggs[AA * AGPAD];   // [a][c], row stride 514
    __shared__ float ubuf[64 * SKPAD];   // wpfS [p][k] chunk; later aliased for k-reduce
    __shared__ float scw[16][16];        // [pg][a]

    int b = blockIdx.x, p0 = blockIdx.y * 64;
    int tid = threadIdx.x;
    int wid = tid >> 5, lane = tid & 31;
    int pg = tid & 15, ag = (tid >> 4) & 3, kg = tid >> 6;

    for (int i = tid; i < EE; i += 256) ssub[i] = subj[b * EE + i];
    if (tid < 64) wattS[tid] = watt[p0 + tid];

    {
        const float4* src = (const float4*)(g_aggr + (size_t)b * AA * CC);
        for (int i4 = tid; i4 < AA * CC / 4; i4 += 256) {
            int a = i4 >> 7, c4 = i4 & 127;
            float4 v = src[i4];
            float* d = aggs + a * AGPAD + c4 * 4;
            d[0] = v.x; d[1] = v.y; d[2] = v.z; d[3] = v.w;
        }
    }
    __syncthreads();

    for (int pi = wid; pi < 64; pi += 8) {
        int p = p0 + pi;
        const float4* w4 = (const float4*)(wps + p * EE);
        const float4* s4 = (const float4*)ssub;
        float s = 0.f;
        #pragma unroll
        for (int i = 0; i < 2; i++) {
            float4 wv = w4[lane + 32 * i], sv = s4[lane + 32 * i];
            s += wv.x * sv.x + wv.y * sv.y + wv.z * sv.z + wv.w * sv.w;
        }
        #pragma unroll
        for (int o = 16; o; o >>= 1) s += __shfl_xor_sync(0xFFFFFFFFu, s, o);
        if (!lane) psall[pi] = s + bps[p] + bpf[p];
    }

    float acc[4][4];   // [i: a][j: p]
    #pragma unroll
    for (int i = 0; i < 4; i++)
        #pragma unroll
        for (int j = 0; j < 4; j++) acc[i][j] = 0.f;

    for (int cc = 0; cc < 8; cc++) {
        int c0 = cc * 64;
        __syncthreads();
        for (int i4 = tid; i4 < 1024; i4 += 256) {
            int p = i4 >> 4, q = i4 & 15;
            float4 v = *(const float4*)(wpf + (size_t)(p0 + p) * CC + c0 + q * 4);
            float* d = ubuf + p * SKPAD + q * 4;
            d[0] = v.x; d[1] = v.y; d[2] = v.z; d[3] = v.w;
        }
        __syncthreads();
        #pragma unroll
        for (int kk = 0; kk < 16; kk++) {
            int k = kg * 16 + kk;
            float wv[4], av[4];
            #pragma unroll
            for (int j = 0; j < 4; j++)
                wv[j] = ubuf[(pg + 16 * j) * SKPAD + k];
            #pragma unroll
            for (int i = 0; i < 4; i++)
                av[i] = aggs[(ag * 4 + i) * AGPAD + c0 + k];
            #pragma unroll
            for (int i = 0; i < 4; i++)
                #pragma unroll
                for (int j = 0; j < 4; j++)
                    acc[i][j] += av[i] * wv[j];
        }
    }
    __syncthreads();

    int tt = pg + 16 * ag;
    {
        float* d = ubuf + (kg * 64 + tt) * 17;
        #pragma unroll
        for (int i = 0; i < 4; i++)
            #pragma unroll
            for (int j = 0; j < 4; j++)
                d[i * 4 + j] = acc[i][j];
    }
    __syncthreads();

    if (kg == 0) {
        float contrib[4] = {0.f, 0.f, 0.f, 0.f};
        #pragma unroll
        for (int j = 0; j < 4; j++) {
            int pl = pg + 16 * j;
            float wt = wattS[pl], pb = psall[pl];
            #pragma unroll
            for (int i = 0; i < 4; i++) {
                float dot = 0.f;
                #pragma unroll
                for (int g = 0; g < 4; g++)
                    dot += ubuf[(g * 64 + tt) * 17 + i * 4 + j];
                contrib[i] += wt * tanhf(dot + pb);
            }
        }
        #pragma unroll
        for (int i = 0; i < 4; i++)
            scw[pg][ag * 4 + i] = contrib[i];
    }
    __syncthreads();
    if (tid < 16) {
        float v = 0.f;
        #pragma unroll
        for (int g = 0; g < 16; g++) v += scw[g][tid];
        g_scorep[blockIdx.y][b * 16 + tid] = v;
    }
}

// ---------------------------------------------------------------------------
// softmax (redundant per block) + weighted sums.  grid (64,5), block 256
__global__ void k_final(float* __restrict__ out) {
    __shared__ float sc[16];
    __shared__ float aw[16];
    int b = blockIdx.x, tid = threadIdx.x;
    if (tid < 16) {
        float v = 0.f;
        #pragma unroll
        for (int j = 0; j < 8; j++) v += g_scorep[j][b * 16 + tid];
        sc[tid] = v;
    }
    __syncthreads();
    if (tid < 16) {
        float m = -1e30f;
        #pragma unroll
        for (int i = 0; i < 16; i++) m = fmaxf(m, sc[i]);
        float sum = 0.f;
        #pragma unroll
        for (int i = 0; i < 16; i++) sum += expf(sc[i] - m);
        aw[tid] = expf(sc[tid] - m) / sum;
    }
    __syncthreads();

    int hw = blockIdx.y * 256 + tid;
    if (hw < HWW) {
        const float* X = out + OFF_X + (size_t)b * AA * HWW;
        float s = 0.f;
        #pragma unroll
        for (int a = 0; a < 16; a++) s += X[a * HWW + hw] * aw[a];
        out[OFF_AX + b * HWW + hw] = s;
        out[OFF_Z + b * 1201 + 1 + hw] = s;
    }
    if (tid == 0 && blockIdx.y == 0) {
        float z = 0.f;
        #pragma unroll
        for (int a = 0; a < 16; a++) z += g_y[b * 16 + a] * aw[a];
        out[OFF_Z + b * 1201] = z;
    }
}

// ---------------------------------------------------------------------------
extern "C" void kernel_launch(void* const* d_in, const int* in_sizes, int n_in,
                              void* d_out, int out_size) {
    const float* enc  = (const float*)d_in[0];
    const float* feat = (const float*)d_in[1];
    const float* subj = (const float*)d_in[2];
    const float* w2   = (const float*)d_in[3];
    const float* b2   = (const float*)d_in[4];
    const float* w3   = (const float*)d_in[5];
    const float* b3   = (const float*)d_in[6];
    const float* wd1  = (const float*)d_in[7];
    const float* bd1  = (const float*)d_in[8];
    const float* wd2  = (const float*)d_in[9];
    const float* bd2  = (const float*)d_in[10];
    const float* wpf  = (const float*)d_in[11];
    const float* bpf  = (const float*)d_in[12];
    const float* wps  = (const float*)d_in[13];
    const float* bps  = (const float*)d_in[14];
    const float* watt = (const float*)d_in[15];
    float* out = (float*)d_out;

    cudaEventRecord(g_evFork, 0);
    cudaStreamWaitEvent(g_s1, g_evFork, 0);

    k_x<<<dim3(64, 10), 128>>>(feat, w3, b3, out);                 // 1 (s0)
    k_aggr<<<dim3(64, NZ), 256>>>(enc, out);                       // 2 (s0)
    k_sumaggr<<<512, 256>>>();                                     // 3 (s0)
    k_score<<<dim3(64, 8), 256>>>(subj, wps, bps, wpf, bpf, watt); // 4 (s0) <- profiled
    k_drt1f<<<dim3(64, 8), 384, 0, g_s1>>>(feat, wd1);             // 5 (s1)
    k_ydrt2<<<64, 512, 0, g_s1>>>(w2, b2, wd2, bd2, bd1, out);     // 6 (s1)

    cudaEventRecord(g_evJoin, g_s1);
    cudaStreamWaitEvent(0, g_evJoin, 0);
    k_final<<<dim3(64, 5), 256>>>(out);                            // 7 (s0)
}

// round 15
// speedup vs baseline: 1.6851x; 1.1787x over previous
#include <cuda_runtime.h>
#include <math.h>

#define BB  64
#define AA  16
#define CC  512
#define HH  30
#define WW  40
#define HWW 1200
#define EE  256
#define PP  512

#define OFF_Z  0
#define OFF_MU 76864
#define OFF_S2 76928
#define OFF_AX 76992
#define OFF_X  153792

#define NZ 15

typedef unsigned long long ull;

#define FMA_F32X2(d, a, b, c) \
    asm("fma.rn.f32x2 %0, %1, %2, %3;" : "=l"(d) : "l"(a), "l"(b), "l"(c))
#define PACK_DUP_F32X2(out, v) \
    asm("mov.b64 %0, {%1, %1};" : "=l"(out) : "f"(v))
#define UNPACK_F32X2(lo, hi, in) \
    asm("mov.b64 {%0, %1}, %2;" : "=f"(lo), "=f"(hi) : "l"(in))

// scratch: every element written each launch before being read (no zeroing needed)
__device__ float g_mean[BB * CC];
__device__ float g_y[BB * AA];
__device__ float g_t1p[8][BB * 48];
__device__ float g_scorep[8][BB * AA];
__device__ float g_aggrp[NZ][BB * AA * CC];
__device__ float g_aggr[BB * AA * CC];
__device__ float g_xp[2][BB * AA * HWW];

// stream + events created once at library load (host-side resources only)
static cudaStream_t g_s1;
static cudaEvent_t g_evFork, g_evJoin;
namespace {
struct InitStreams {
    InitStreams() {
        cudaStreamCreateWithFlags(&g_s1, cudaStreamNonBlocking);
        cudaEventCreateWithFlags(&g_evFork, cudaEventDisableTiming);
        cudaEventCreateWithFlags(&g_evJoin, cudaEventDisableTiming);
    }
};
InitStreams g_initStreams;
}

// ---------------------------------------------------------------------------
// x partials: grid (64, 10, 2), block 128.  z = c-half (256 channels).
// Same f32x2 inner pattern as the R12 winner; raw partial sums (no bias/relu).
__global__ void __launch_bounds__(128) k_xp(const float* __restrict__ F,
                                            const float* __restrict__ w3) {
    __shared__ float ws[256 * AA];  // transposed [c][a] for this half
    int b = blockIdx.x, tid = threadIdx.x;
    int ch0 = blockIdx.z * 256;
    for (int i = tid; i < 256 * AA; i += 128)
        ws[i] = w3[(i & 15) * CC + ch0 + (i >> 4)];
    __syncthreads();

    int hw = blockIdx.y * 128 + tid;
    bool v = hw < HWW;
    int hwl = v ? hw : 0;
    const float* Fb = F + (size_t)b * CC * HWW + (size_t)ch0 * HWW + hwl;

    ull acc[8];
    #pragma unroll
    for (int j = 0; j < 8; j++) acc[j] = 0ULL;

    #pragma unroll 4
    for (int c = 0; c < 256; c++) {
        float f = Fb[c * HWW];
        ull f2; PACK_DUP_F32X2(f2, f);
        const ulonglong2* wp = (const ulonglong2*)(ws + c * 16);
        ulonglong2 wA = wp[0];
        ulonglong2 wB = wp[1];
        ulonglong2 wC = wp[2];
        ulonglong2 wD = wp[3];
        FMA_F32X2(acc[0], f2, wA.x, acc[0]);
        FMA_F32X2(acc[1], f2, wA.y, acc[1]);
        FMA_F32X2(acc[2], f2, wB.x, acc[2]);
        FMA_F32X2(acc[3], f2, wB.y, acc[3]);
        FMA_F32X2(acc[4], f2, wC.x, acc[4]);
        FMA_F32X2(acc[5], f2, wC.y, acc[5]);
        FMA_F32X2(acc[6], f2, wD.x, acc[6]);
        FMA_F32X2(acc[7], f2, wD.y, acc[7]);
    }

    if (v) {
        float* X = g_xp[blockIdx.z] + (size_t)b * AA * HWW + hw;
        #pragma unroll
        for (int j = 0; j < 8; j++) {
            float lo, hi;
            UNPACK_F32X2(lo, hi, acc[j]);
            X[(2 * j + 0) * HWW] = lo;
            X[(2 * j + 1) * HWW] = hi;
        }
    }
}

// ---------------------------------------------------------------------------
// combine x partials: X = relu(p0 + p1 + bias).  grid 4800, block 256.
__global__ void __launch_bounds__(256) k_xcomb(const float* __restrict__ b3,
                                               float* __restrict__ out) {
    int i = blockIdx.x * 256 + threadIdx.x;
    if (i < BB * AA * HWW) {
        int a = (i / HWW) & 15;
        out[OFF_X + i] = fmaxf(g_xp[0][i] + g_xp[1][i] + b3[a], 0.f);
    }
}

// ---------------------------------------------------------------------------
// Fused drt1 conv partials + per-channel mean of F.  grid (64, 8), block 384
__global__ void __launch_bounds__(384) k_drt1f(const float* __restrict__ F,
                                               const float* __restrict__ w1) {
    __shared__ float ch[2][HWW];
    __shared__ float wsh[64 * 49];
    __shared__ float csum[2][12];
    __shared__ float pos_acc[336];

    int chunkid = blockIdx.y;
    int b = blockIdx.x, c0 = chunkid * 64;
    int tid = threadIdx.x;
    int wid = tid >> 5, lane = tid & 31;

    for (int i = tid; i < 64 * 49; i += 384) wsh[i] = w1[c0 * 49 + i];

    int pos = tid / 7, kh = tid - pos * 7;
    bool active = tid < 336;
    int oh = pos >> 3, ow = pos & 7;
    int ih = oh * 5 - 2 + kh;
    int iw0 = ow * 5 - 2;
    bool ihok = active && ih >= 0;

    const float* Fb = F + ((size_t)b * CC + c0) * HWW;

    {
        float ps = 0.f;
        if (tid < 300) {
            float4 v = ((const float4*)Fb)[tid];
            ((float4*)ch[0])[tid] = v;
            ps = v.x + v.y + v.z + v.w;
        }
        #pragma unroll
        for (int o = 16; o; o >>= 1) ps += __shfl_xor_sync(0xFFFFFFFFu, ps, o);
        if (!lane) csum[0][wid] = ps;
    }
    __syncthreads();

    float acc = 0.f;
    for (int c = 0; c < 64; c++) {
        int cur = c & 1;
        if (c < 63) {
            float ps = 0.f;
            if (tid < 300) {
                float4 v = ((const float4*)(Fb + (size_t)(c + 1) * HWW))[tid];
                ((float4*)ch[cur ^ 1])[tid] = v;
                ps = v.x + v.y + v.z + v.w;
            }
            #pragma unroll
            for (int o = 16; o; o >>= 1) ps += __shfl_xor_sync(0xFFFFFFFFu, ps, o);
            if (!lane) csum[cur ^ 1][wid] = ps;
        }
        if (tid == 0) {
            float m = 0.f;
            #pragma unroll
            for (int w = 0; w < 12; w++) m += csum[cur][w];
            g_mean[b * CC + c0 + c] = m * (1.f / HWW);
        }
        if (ihok) {
            const float* row = ch[cur] + ih * WW;
            const float* wr = wsh + c * 49 + kh * 7;
            #pragma unroll
            for (int kw = 0; kw < 7; kw++) {
                int iw = iw0 + kw;
                if (iw >= 0) acc += row[iw] * wr[kw];
            }
        }
        __syncthreads();
    }

    if (active) pos_acc[tid] = acc;
    __syncthreads();
    if (active && kh == 0) {
        float s = pos_acc[tid] + pos_acc[tid + 1] + pos_acc[tid + 2]
                + pos_acc[tid + 3] + pos_acc[tid + 4] + pos_acc[tid + 5]
                + pos_acc[tid + 6];
        g_t1p[chunkid][b * 48 + pos] = s;
    }
}

// ---------------------------------------------------------------------------
// merged y + drt2.  grid 64, block 512
__global__ void __launch_bounds__(512) k_ydrt2(
    const float* __restrict__ w2, const float* __restrict__ b2,
    const float* __restrict__ wd2, const float* __restrict__ bd2,
    const float* __restrict__ bd1, float* __restrict__ out) {
    __shared__ float t1s[48];
    int b = blockIdx.x, tid = threadIdx.x;
    int a = tid >> 5, lane = tid & 31;

    if (tid < 48) {
        float t = 0.f;
        #pragma unroll
        for (int j = 0; j < 8; j++) t += g_t1p[j][b * 48 + tid];
        t1s[tid] = fmaxf(t + bd1[0], 0.f);
    }

    const float4* m4 = (const float4*)(g_mean + b * CC);
    const float4* w4 = (const float4*)(w2 + a * CC);
    float s = 0.f;
    #pragma unroll
    for (int i = 0; i < 4; i++) {
        float4 mv = m4[lane + 32 * i];
        float4 wv = w4[lane + 32 * i];
        s += mv.x * wv.x + mv.y * wv.y + mv.z * wv.z + mv.w * wv.w;
    }
    #pragma unroll
    for (int o = 16; o; o >>= 1) s += __shfl_xor_sync(0xFFFFFFFFu, s, o);
    if (!lane) g_y[b * AA + a] = s + b2[a];

    __syncthreads();
    if (tid < 64) {
        int o = tid >> 5;
        float s2 = 0.f;
        for (int i = lane; i < 48; i += 32) s2 += t1s[i] * wd2[o * 48 + i];
        #pragma unroll
        for (int sh = 16; sh; sh >>= 1) s2 += __shfl_xor_sync(0xFFFFFFFFu, s2, sh);
        if (!lane) {
            float v = s2 + bd2[o];
            if (o == 0) out[OFF_MU + b] = v;
            else        out[OFF_S2 + b] = expf(v);
        }
    }
}

// ---------------------------------------------------------------------------
// aggr partial v3: grid (64, NZ), block 256.  hw slice 80, 4 chunks of ACH=20.
#define ACH 20
__global__ void __launch_bounds__(256) k_aggr(const float* __restrict__ Eenc,
                                              const float* __restrict__ out) {
    __shared__ float Esh[ACH * 512];     // [k][c]
    __shared__ float Xsh[ACH * 16];      // [k][a]
    int b = blockIdx.x;
    int z = blockIdx.y;
    int tid = threadIdx.x;
    int tc = tid & 63;
    int ta = tid >> 6;

    const float* Eb = Eenc + (size_t)b * CC * HWW;
    const float* Xb = out + OFF_X + (size_t)b * AA * HWW;

    float acc[4][8];
    #pragma unroll
    for (int i = 0; i < 4; i++)
        #pragma unroll
        for (int j = 0; j < 8; j++) acc[i][j] = 0.f;

    int hwbase = z * 80;
    for (int chk = 0; chk < 4; chk++) {
        int k0 = hwbase + chk * ACH;
        #pragma unroll
        for (int r = 0; r < 2; r++) {
            int c = tid + r * 256;
            const float4* Er = (const float4*)(Eb + (size_t)c * HWW + k0);
            #pragma unroll
            for (int q = 0; q < 5; q++) {
                float4 v = Er[q];
                Esh[(q * 4 + 0) * 512 + c] = v.x;
                Esh[(q * 4 + 1) * 512 + c] = v.y;
                Esh[(q * 4 + 2) * 512 + c] = v.z;
                Esh[(q * 4 + 3) * 512 + c] = v.w;
            }
        }
        if (tid < 80) {
            int aa = tid / 5, q = tid % 5;
            float4 v = *(const float4*)(Xb + aa * HWW + k0 + q * 4);
            Xsh[(q * 4 + 0) * 16 + aa] = v.x;
            Xsh[(q * 4 + 1) * 16 + aa] = v.y;
            Xsh[(q * 4 + 2) * 16 + aa] = v.z;
            Xsh[(q * 4 + 3) * 16 + aa] = v.w;
        }
        __syncthreads();
        #pragma unroll
        for (int k = 0; k < ACH; k++) {
            float4 e0 = *(const float4*)(Esh + k * 512 + tc * 4);
            float4 e1 = *(const float4*)(Esh + k * 512 + 256 + tc * 4);
            float4 xv = *(const float4*)(Xsh + k * 16 + ta * 4);
            float ev[8] = {e0.x, e0.y, e0.z, e0.w, e1.x, e1.y, e1.z, e1.w};
            float xa[4] = {xv.x, xv.y, xv.z, xv.w};
            #pragma unroll
            for (int i = 0; i < 4; i++)
                #pragma unroll
                for (int j = 0; j < 8; j++)
                    acc[i][j] += xa[i] * ev[j];
        }
        __syncthreads();
    }

    float* dst = g_aggrp[z] + (size_t)b * AA * CC;
    #pragma unroll
    for (int i = 0; i < 4; i++) {
        int a = ta * 4 + i;
        float4 s0, s1;
        s0.x = acc[i][0] * (1.f / HWW); s0.y = acc[i][1] * (1.f / HWW);
        s0.z = acc[i][2] * (1.f / HWW); s0.w = acc[i][3] * (1.f / HWW);
        s1.x = acc[i][4] * (1.f / HWW); s1.y = acc[i][5] * (1.f / HWW);
        s1.z = acc[i][6] * (1.f / HWW); s1.w = acc[i][7] * (1.f / HWW);
        *(float4*)(dst + a * CC + tc * 4) = s0;
        *(float4*)(dst + a * CC + 256 + tc * 4) = s1;
    }
}

// ---------------------------------------------------------------------------
// reduce NZ aggr partials -> g_aggr.  grid 512, block 256, float4 per thread.
__global__ void __launch_bounds__(256) k_sumaggr() {
    int i4 = blockIdx.x * 256 + threadIdx.x;     // 131072 float4s
    float4 s = ((const float4*)g_aggrp[0])[i4];
    #pragma unroll
    for (int z = 1; z < NZ; z++) {
        float4 v = ((const float4*)g_aggrp[z])[i4];
        s.x += v.x; s.y += v.y; s.z += v.z; s.w += v.w;
    }
    ((float4*)g_aggr)[i4] = s;
}

// ---------------------------------------------------------------------------
// attention scores v2 — register-tiled GEMM.
// grid (64, 8): (b, 64-p chunk).  block 256 = 16 pg x 4 ag x 4 kg.
#define AGPAD 514
#define SKPAD 69
__global__ void __launch_bounds__(256) k_score(
    const float* __restrict__ subj, const float* __restrict__ wps,
    const float* __restrict__ bps, const float* __restrict__ wpf,
    const float* __restrict__ bpf, const float* __restrict__ watt) {
    __shared__ float ssub[EE];
    __shared__ float psall[64];          // proj_s + bps + bpf
    __shared__ float wattS[64];
    __shared__ float aggs[AA * AGPAD];   // [a][c], row stride 514
    __shared__ float ubuf[64 * SKPAD];   // wpfS [p][k] chunk; later aliased for k-reduce
    __shared__ float scw[16][16];        // [pg][a]

    int b = blockIdx.x, p0 = blockIdx.y * 64;
    int tid = threadIdx.x;
    int wid = tid >> 5, lane = tid & 31;
    int pg = tid & 15, ag = (tid >> 4) & 3, kg = tid >> 6;

    for (int i = tid; i < EE; i += 256) ssub[i] = subj[b * EE + i];
    if (tid < 64) wattS[tid] = watt[p0 + tid];

    {
        const float4* src = (const float4*)(g_aggr + (size_t)b * AA * CC);
        for (int i4 = tid; i4 < AA * CC / 4; i4 += 256) {
            int a = i4 >> 7, c4 = i4 & 127;
            float4 v = src[i4];
            float* d = aggs + a * AGPAD + c4 * 4;
            d[0] = v.x; d[1] = v.y; d[2] = v.z; d[3] = v.w;
        }
    }
    __syncthreads();

    for (int pi = wid; pi < 64; pi += 8) {
        int p = p0 + pi;
        const float4* w4 = (const float4*)(wps + p * EE);
        const float4* s4 = (const float4*)ssub;
        float s = 0.f;
        #pragma unroll
        for (int i = 0; i < 2; i++) {
            float4 wv = w4[lane + 32 * i], sv = s4[lane + 32 * i];
            s += wv.x * sv.x + wv.y * sv.y + wv.z * sv.z + wv.w * sv.w;
        }
        #pragma unroll
        for (int o = 16; o; o >>= 1) s += __shfl_xor_sync(0xFFFFFFFFu, s, o);
        if (!lane) psall[pi] = s + bps[p] + bpf[p];
    }

    float acc[4][4];   // [i: a][j: p]
    #pragma unroll
    for (int i = 0; i < 4; i++)
        #pragma unroll
        for (int j = 0; j < 4; j++) acc[i][j] = 0.f;

    for (int cc = 0; cc < 8; cc++) {
        int c0 = cc * 64;
        __syncthreads();
        for (int i4 = tid; i4 < 1024; i4 += 256) {
            int p = i4 >> 4, q = i4 & 15;
            float4 v = *(const float4*)(wpf + (size_t)(p0 + p) * CC + c0 + q * 4);
            float* d = ubuf + p * SKPAD + q * 4;
            d[0] = v.x; d[1] = v.y; d[2] = v.z; d[3] = v.w;
        }
        __syncthreads();
        #pragma unroll
        for (int kk = 0; kk < 16; kk++) {
            int k = kg * 16 + kk;
            float wv[4], av[4];
            #pragma unroll
            for (int j = 0; j < 4; j++)
                wv[j] = ubuf[(pg + 16 * j) * SKPAD + k];
            #pragma unroll
            for (int i = 0; i < 4; i++)
                av[i] = aggs[(ag * 4 + i) * AGPAD + c0 + k];
            #pragma unroll
            for (int i = 0; i < 4; i++)
                #pragma unroll
                for (int j = 0; j < 4; j++)
                    acc[i][j] += av[i] * wv[j];
        }
    }
    __syncthreads();

    int tt = pg + 16 * ag;
    {
        float* d = ubuf + (kg * 64 + tt) * 17;
        #pragma unroll
        for (int i = 0; i < 4; i++)
            #pragma unroll
            for (int j = 0; j < 4; j++)
                d[i * 4 + j] = acc[i][j];
    }
    __syncthreads();

    if (kg == 0) {
        float contrib[4] = {0.f, 0.f, 0.f, 0.f};
        #pragma unroll
        for (int j = 0; j < 4; j++) {
            int pl = pg + 16 * j;
            float wt = wattS[pl], pb = psall[pl];
            #pragma unroll
            for (int i = 0; i < 4; i++) {
                float dot = 0.f;
                #pragma unroll
                for (int g = 0; g < 4; g++)
                    dot += ubuf[(g * 64 + tt) * 17 + i * 4 + j];
                contrib[i] += wt * tanhf(dot + pb);
            }
        }
        #pragma unroll
        for (int i = 0; i < 4; i++)
            scw[pg][ag * 4 + i] = contrib[i];
    }
    __syncthreads();
    if (tid < 16) {
        float v = 0.f;
        #pragma unroll
        for (int g = 0; g < 16; g++) v += scw[g][tid];
        g_scorep[blockIdx.y][b * 16 + tid] = v;
    }
}

// ---------------------------------------------------------------------------
// softmax (redundant per block) + weighted sums.  grid (64,5), block 256
__global__ void k_final(float* __restrict__ out) {
    __shared__ float sc[16];
    __shared__ float aw[16];
    int b = blockIdx.x, tid = threadIdx.x;
    if (tid < 16) {
        float v = 0.f;
        #pragma unroll
        for (int j = 0; j < 8; j++) v += g_scorep[j][b * 16 + tid];
        sc[tid] = v;
    }
    __syncthreads();
    if (tid < 16) {
        float m = -1e30f;
        #pragma unroll
        for (int i = 0; i < 16; i++) m = fmaxf(m, sc[i]);
        float sum = 0.f;
        #pragma unroll
        for (int i = 0; i < 16; i++) sum += expf(sc[i] - m);
        aw[tid] = expf(sc[tid] - m) / sum;
    }
    __syncthreads();

    int hw = blockIdx.y * 256 + tid;
    if (hw < HWW) {
        const float* X = out + OFF_X + (size_t)b * AA * HWW;
        float s = 0.f;
        #pragma unroll
        for (int a = 0; a < 16; a++) s += X[a * HWW + hw] * aw[a];
        out[OFF_AX + b * HWW + hw] = s;
        out[OFF_Z + b * 1201 + 1 + hw] = s;
    }
    if (tid == 0 && blockIdx.y == 0) {
        float z = 0.f;
        #pragma unroll
        for (int a = 0; a < 16; a++) z += g_y[b * 16 + a] * aw[a];
        out[OFF_Z + b * 1201] = z;
    }
}

// ---------------------------------------------------------------------------
extern "C" void kernel_launch(void* const* d_in, const int* in_sizes, int n_in,
                              void* d_out, int out_size) {
    const float* enc  = (const float*)d_in[0];
    const float* feat = (const float*)d_in[1];
    const float* subj = (const float*)d_in[2];
    const float* w2   = (const float*)d_in[3];
    const float* b2   = (const float*)d_in[4];
    const float* w3   = (const float*)d_in[5];
    const float* b3   = (const float*)d_in[6];
    const float* wd1  = (const float*)d_in[7];
    const float* bd1  = (const float*)d_in[8];
    const float* wd2  = (const float*)d_in[9];
    const float* bd2  = (const float*)d_in[10];
    const float* wpf  = (const float*)d_in[11];
    const float* bpf  = (const float*)d_in[12];
    const float* wps  = (const float*)d_in[13];
    const float* bps  = (const float*)d_in[14];
    const float* watt = (const float*)d_in[15];
    float* out = (float*)d_out;

    cudaEventRecord(g_evFork, 0);
    cudaStreamWaitEvent(g_s1, g_evFork, 0);

    k_xp<<<dim3(64, 10, 2), 128>>>(feat, w3);                      // 1 (s0)
    k_xcomb<<<4800, 256>>>(b3, out);                               // 2 (s0)
    k_aggr<<<dim3(64, NZ), 256>>>(enc, out);                       // 3 (s0)
    k_sumaggr<<<512, 256>>>();                                     // 4 (s0) <- profiled
    k_score<<<dim3(64, 8), 256>>>(subj, wps, bps, wpf, bpf, watt); // 5 (s0)
    k_drt1f<<<dim3(64, 8), 384, 0, g_s1>>>(feat, wd1);             // 6 (s1)
    k_ydrt2<<<64, 512, 0, g_s1>>>(w2, b2, wd2, bd2, bd1, out);     // 7 (s1)

    cudaEventRecord(g_evJoin, g_s1);
    cudaStreamWaitEvent(0, g_evJoin, 0);
    k_final<<<dim3(64, 5), 256>>>(out);                            // 8 (s0)
}

// round 16
// speedup vs baseline: 1.6902x; 1.0030x over previous
#include <cuda_runtime.h>
#include <math.h>

#define BB  64
#define AA  16
#define CC  512
#define HH  30
#define WW  40
#define HWW 1200
#define EE  256
#define PP  512

#define OFF_Z  0
#define OFF_MU 76864
#define OFF_S2 76928
#define OFF_AX 76992
#define OFF_X  153792

#define NZ 15

typedef unsigned long long ull;

#define FMA_F32X2(d, a, b, c) \
    asm("fma.rn.f32x2 %0, %1, %2, %3;" : "=l"(d) : "l"(a), "l"(b), "l"(c))
#define PACK_DUP_F32X2(out, v) \
    asm("mov.b64 %0, {%1, %1};" : "=l"(out) : "f"(v))
#define UNPACK_F32X2(lo, hi, in) \
    asm("mov.b64 {%0, %1}, %2;" : "=f"(lo), "=f"(hi) : "l"(in))

// scratch: every element written each launch before being read (no zeroing needed)
__device__ float g_mean[BB * CC];
__device__ float g_y[BB * AA];
__device__ float g_t1p[8][BB * 48];
__device__ float g_scorep[8][BB * AA];
__device__ float g_aggrp[NZ][BB * AA * CC];
__device__ float g_aggr[BB * AA * CC];
__device__ float g_xp[2][BB * AA * HWW];

// stream + events created once at library load (host-side resources only)
static cudaStream_t g_s1;
static cudaEvent_t g_evFork, g_evJoin, g_evXp;
namespace {
struct InitStreams {
    InitStreams() {
        cudaStreamCreateWithFlags(&g_s1, cudaStreamNonBlocking);
        cudaEventCreateWithFlags(&g_evFork, cudaEventDisableTiming);
        cudaEventCreateWithFlags(&g_evJoin, cudaEventDisableTiming);
        cudaEventCreateWithFlags(&g_evXp, cudaEventDisableTiming);
    }
};
InitStreams g_initStreams;
}

// ---------------------------------------------------------------------------
// x partials: grid (64, 10, 2), block 128.  z = c-half (256 channels).
__global__ void __launch_bounds__(128) k_xp(const float* __restrict__ F,
                                            const float* __restrict__ w3) {
    __shared__ float ws[256 * AA];  // transposed [c][a] for this half
    int b = blockIdx.x, tid = threadIdx.x;
    int ch0 = blockIdx.z * 256;
    for (int i = tid; i < 256 * AA; i += 128)
        ws[i] = w3[(i & 15) * CC + ch0 + (i >> 4)];
    __syncthreads();

    int hw = blockIdx.y * 128 + tid;
    bool v = hw < HWW;
    int hwl = v ? hw : 0;
    const float* Fb = F + (size_t)b * CC * HWW + (size_t)ch0 * HWW + hwl;

    ull acc[8];
    #pragma unroll
    for (int j = 0; j < 8; j++) acc[j] = 0ULL;

    #pragma unroll 4
    for (int c = 0; c < 256; c++) {
        float f = Fb[c * HWW];
        ull f2; PACK_DUP_F32X2(f2, f);
        const ulonglong2* wp = (const ulonglong2*)(ws + c * 16);
        ulonglong2 wA = wp[0];
        ulonglong2 wB = wp[1];
        ulonglong2 wC = wp[2];
        ulonglong2 wD = wp[3];
        FMA_F32X2(acc[0], f2, wA.x, acc[0]);
        FMA_F32X2(acc[1], f2, wA.y, acc[1]);
        FMA_F32X2(acc[2], f2, wB.x, acc[2]);
        FMA_F32X2(acc[3], f2, wB.y, acc[3]);
        FMA_F32X2(acc[4], f2, wC.x, acc[4]);
        FMA_F32X2(acc[5], f2, wC.y, acc[5]);
        FMA_F32X2(acc[6], f2, wD.x, acc[6]);
        FMA_F32X2(acc[7], f2, wD.y, acc[7]);
    }

    if (v) {
        float* X = g_xp[blockIdx.z] + (size_t)b * AA * HWW + hw;
        #pragma unroll
        for (int j = 0; j < 8; j++) {
            float lo, hi;
            UNPACK_F32X2(lo, hi, acc[j]);
            X[(2 * j + 0) * HWW] = lo;
            X[(2 * j + 1) * HWW] = hi;
        }
    }
}

// ---------------------------------------------------------------------------
// combine x partials: X = relu(p0 + p1 + bias) -> out.  grid 4800, block 256.
// Runs on s1 (off the critical path); out X consumed only by k_final after join.
__global__ void __launch_bounds__(256) k_xcomb(const float* __restrict__ b3,
                                               float* __restrict__ out) {
    int i = blockIdx.x * 256 + threadIdx.x;
    if (i < BB * AA * HWW) {
        int a = (i / HWW) & 15;
        out[OFF_X + i] = fmaxf(g_xp[0][i] + g_xp[1][i] + b3[a], 0.f);
    }
}

// ---------------------------------------------------------------------------
// Fused drt1 conv partials + per-channel mean of F.  grid (64, 8), block 384
__global__ void __launch_bounds__(384) k_drt1f(const float* __restrict__ F,
                                               const float* __restrict__ w1) {
    __shared__ float ch[2][HWW];
    __shared__ float wsh[64 * 49];
    __shared__ float csum[2][12];
    __shared__ float pos_acc[336];

    int chunkid = blockIdx.y;
    int b = blockIdx.x, c0 = chunkid * 64;
    int tid = threadIdx.x;
    int wid = tid >> 5, lane = tid & 31;

    for (int i = tid; i < 64 * 49; i += 384) wsh[i] = w1[c0 * 49 + i];

    int pos = tid / 7, kh = tid - pos * 7;
    bool active = tid < 336;
    int oh = pos >> 3, ow = pos & 7;
    int ih = oh * 5 - 2 + kh;
    int iw0 = ow * 5 - 2;
    bool ihok = active && ih >= 0;

    const float* Fb = F + ((size_t)b * CC + c0) * HWW;

    {
        float ps = 0.f;
        if (tid < 300) {
            float4 v = ((const float4*)Fb)[tid];
            ((float4*)ch[0])[tid] = v;
            ps = v.x + v.y + v.z + v.w;
        }
        #pragma unroll
        for (int o = 16; o; o >>= 1) ps += __shfl_xor_sync(0xFFFFFFFFu, ps, o);
        if (!lane) csum[0][wid] = ps;
    }
    __syncthreads();

    float acc = 0.f;
    for (int c = 0; c < 64; c++) {
        int cur = c & 1;
        if (c < 63) {
            float ps = 0.f;
            if (tid < 300) {
                float4 v = ((const float4*)(Fb + (size_t)(c + 1) * HWW))[tid];
                ((float4*)ch[cur ^ 1])[tid] = v;
                ps = v.x + v.y + v.z + v.w;
            }
            #pragma unroll
            for (int o = 16; o; o >>= 1) ps += __shfl_xor_sync(0xFFFFFFFFu, ps, o);
            if (!lane) csum[cur ^ 1][wid] = ps;
        }
        if (tid == 0) {
            float m = 0.f;
            #pragma unroll
            for (int w = 0; w < 12; w++) m += csum[cur][w];
            g_mean[b * CC + c0 + c] = m * (1.f / HWW);
        }
        if (ihok) {
            const float* row = ch[cur] + ih * WW;
            const float* wr = wsh + c * 49 + kh * 7;
            #pragma unroll
            for (int kw = 0; kw < 7; kw++) {
                int iw = iw0 + kw;
                if (iw >= 0) acc += row[iw] * wr[kw];
            }
        }
        __syncthreads();
    }

    if (active) pos_acc[tid] = acc;
    __syncthreads();
    if (active && kh == 0) {
        float s = pos_acc[tid] + pos_acc[tid + 1] + pos_acc[tid + 2]
                + pos_acc[tid + 3] + pos_acc[tid + 4] + pos_acc[tid + 5]
                + pos_acc[tid + 6];
        g_t1p[chunkid][b * 48 + pos] = s;
    }
}

// ---------------------------------------------------------------------------
// merged y + drt2.  grid 64, block 512
__global__ void __launch_bounds__(512) k_ydrt2(
    const float* __restrict__ w2, const float* __restrict__ b2,
    const float* __restrict__ wd2, const float* __restrict__ bd2,
    const float* __restrict__ bd1, float* __restrict__ out) {
    __shared__ float t1s[48];
    int b = blockIdx.x, tid = threadIdx.x;
    int a = tid >> 5, lane = tid & 31;

    if (tid < 48) {
        float t = 0.f;
        #pragma unroll
        for (int j = 0; j < 8; j++) t += g_t1p[j][b * 48 + tid];
        t1s[tid] = fmaxf(t + bd1[0], 0.f);
    }

    const float4* m4 = (const float4*)(g_mean + b * CC);
    const float4* w4 = (const float4*)(w2 + a * CC);
    float s = 0.f;
    #pragma unroll
    for (int i = 0; i < 4; i++) {
        float4 mv = m4[lane + 32 * i];
        float4 wv = w4[lane + 32 * i];
        s += mv.x * wv.x + mv.y * wv.y + mv.z * wv.z + mv.w * wv.w;
    }
    #pragma unroll
    for (int o = 16; o; o >>= 1) s += __shfl_xor_sync(0xFFFFFFFFu, s, o);
    if (!lane) g_y[b * AA + a] = s + b2[a];

    __syncthreads();
    if (tid < 64) {
        int o = tid >> 5;
        float s2 = 0.f;
        for (int i = lane; i < 48; i += 32) s2 += t1s[i] * wd2[o * 48 + i];
        #pragma unroll
        for (int sh = 16; sh; sh >>= 1) s2 += __shfl_xor_sync(0xFFFFFFFFu, s2, sh);
        if (!lane) {
            float v = s2 + bd2[o];
            if (o == 0) out[OFF_MU + b] = v;
            else        out[OFF_S2 + b] = expf(v);
        }
    }
}

// ---------------------------------------------------------------------------
// aggr partial: grid (64, NZ), block 256.  X computed inline from partials.
#define ACH 20
__global__ void __launch_bounds__(256) k_aggr(const float* __restrict__ Eenc,
                                              const float* __restrict__ b3) {
    __shared__ float Esh[ACH * 512];     // [k][c]
    __shared__ float Xsh[ACH * 16];      // [k][a]
    __shared__ float b3s[16];
    int b = blockIdx.x;
    int z = blockIdx.y;
    int tid = threadIdx.x;
    int tc = tid & 63;
    int ta = tid >> 6;

    if (tid < 16) b3s[tid] = b3[tid];

    const float* Eb = Eenc + (size_t)b * CC * HWW;
    const float* X0 = g_xp[0] + (size_t)b * AA * HWW;
    const float* X1 = g_xp[1] + (size_t)b * AA * HWW;

    float acc[4][8];
    #pragma unroll
    for (int i = 0; i < 4; i++)
        #pragma unroll
        for (int j = 0; j < 8; j++) acc[i][j] = 0.f;

    __syncthreads();   // b3s visible

    int hwbase = z * 80;
    for (int chk = 0; chk < 4; chk++) {
        int k0 = hwbase + chk * ACH;
        #pragma unroll
        for (int r = 0; r < 2; r++) {
            int c = tid + r * 256;
            const float4* Er = (const float4*)(Eb + (size_t)c * HWW + k0);
            #pragma unroll
            for (int q = 0; q < 5; q++) {
                float4 v = Er[q];
                Esh[(q * 4 + 0) * 512 + c] = v.x;
                Esh[(q * 4 + 1) * 512 + c] = v.y;
                Esh[(q * 4 + 2) * 512 + c] = v.z;
                Esh[(q * 4 + 3) * 512 + c] = v.w;
            }
        }
        if (tid < 80) {
            int aa = tid / 5, q = tid % 5;
            size_t off = (size_t)aa * HWW + k0 + q * 4;
            float4 p0 = *(const float4*)(X0 + off);
            float4 p1 = *(const float4*)(X1 + off);
            float bias = b3s[aa];
            float4 v;
            v.x = fmaxf(p0.x + p1.x + bias, 0.f);
            v.y = fmaxf(p0.y + p1.y + bias, 0.f);
            v.z = fmaxf(p0.z + p1.z + bias, 0.f);
            v.w = fmaxf(p0.w + p1.w + bias, 0.f);
            Xsh[(q * 4 + 0) * 16 + aa] = v.x;
            Xsh[(q * 4 + 1) * 16 + aa] = v.y;
            Xsh[(q * 4 + 2) * 16 + aa] = v.z;
            Xsh[(q * 4 + 3) * 16 + aa] = v.w;
        }
        __syncthreads();
        #pragma unroll
        for (int k = 0; k < ACH; k++) {
            float4 e0 = *(const float4*)(Esh + k * 512 + tc * 4);
            float4 e1 = *(const float4*)(Esh + k * 512 + 256 + tc * 4);
            float4 xv = *(const float4*)(Xsh + k * 16 + ta * 4);
            float ev[8] = {e0.x, e0.y, e0.z, e0.w, e1.x, e1.y, e1.z, e1.w};
            float xa[4] = {xv.x, xv.y, xv.z, xv.w};
            #pragma unroll
            for (int i = 0; i < 4; i++)
                #pragma unroll
                for (int j = 0; j < 8; j++)
                    acc[i][j] += xa[i] * ev[j];
        }
        __syncthreads();
    }

    float* dst = g_aggrp[z] + (size_t)b * AA * CC;
    #pragma unroll
    for (int i = 0; i < 4; i++) {
        int a = ta * 4 + i;
        float4 s0, s1;
        s0.x = acc[i][0] * (1.f / HWW); s0.y = acc[i][1] * (1.f / HWW);
        s0.z = acc[i][2] * (1.f / HWW); s0.w = acc[i][3] * (1.f / HWW);
        s1.x = acc[i][4] * (1.f / HWW); s1.y = acc[i][5] * (1.f / HWW);
        s1.z = acc[i][6] * (1.f / HWW); s1.w = acc[i][7] * (1.f / HWW);
        *(float4*)(dst + a * CC + tc * 4) = s0;
        *(float4*)(dst + a * CC + 256 + tc * 4) = s1;
    }
}

// ---------------------------------------------------------------------------
// reduce NZ aggr partials -> g_aggr.  grid 512, block 256, float4 per thread.
__global__ void __launch_bounds__(256) k_sumaggr() {
    int i4 = blockIdx.x * 256 + threadIdx.x;     // 131072 float4s
    float4 s = ((const float4*)g_aggrp[0])[i4];
    #pragma unroll
    for (int z = 1; z < NZ; z++) {
        float4 v = ((const float4*)g_aggrp[z])[i4];
        s.x += v.x; s.y += v.y; s.z += v.z; s.w += v.w;
    }
    ((float4*)g_aggr)[i4] = s;
}

// ---------------------------------------------------------------------------
// attention scores v2 — register-tiled GEMM.
// grid (64, 8): (b, 64-p chunk).  block 256 = 16 pg x 4 ag x 4 kg.
#define AGPAD 514
#define SKPAD 69
__global__ void __launch_bounds__(256) k_score(
    const float* __restrict__ subj, const float* __restrict__ wps,
    const float* __restrict__ bps, const float* __restrict__ wpf,
    const float* __restrict__ bpf, const float* __restrict__ watt) {
    __shared__ float ssub[EE];
    __shared__ float psall[64];          // proj_s + bps + bpf
    __shared__ float wattS[64];
    __shared__ float aggs[AA * AGPAD];   // [a][c], row stride 514
    __shared__ float ubuf[64 * SKPAD];   // wpfS [p][k] chunk; later aliased for k-reduce
    __shared__ float scw[16][16];        // [pg][a]

    int b = blockIdx.x, p0 = blockIdx.y * 64;
    int tid = threadIdx.x;
    int wid = tid >> 5, lane = tid & 31;
    int pg = tid & 15, ag = (tid >> 4) & 3, kg = tid >> 6;

    for (int i = tid; i < EE; i += 256) ssub[i] = subj[b * EE + i];
    if (tid < 64) wattS[tid] = watt[p0 + tid];

    {
        const float4* src = (const float4*)(g_aggr + (size_t)b * AA * CC);
        for (int i4 = tid; i4 < AA * CC / 4; i4 += 256) {
            int a = i4 >> 7, c4 = i4 & 127;
            float4 v = src[i4];
            float* d = aggs + a * AGPAD + c4 * 4;
            d[0] = v.x; d[1] = v.y; d[2] = v.z; d[3] = v.w;
        }
    }
    __syncthreads();

    for (int pi = wid; pi < 64; pi += 8) {
        int p = p0 + pi;
        const float4* w4 = (const float4*)(wps + p * EE);
        const float4* s4 = (const float4*)ssub;
        float s = 0.f;
        #pragma unroll
        for (int i = 0; i < 2; i++) {
            float4 wv = w4[lane + 32 * i], sv = s4[lane + 32 * i];
            s += wv.x * sv.x + wv.y * sv.y + wv.z * sv.z + wv.w * sv.w;
        }
        #pragma unroll
        for (int o = 16; o; o >>= 1) s += __shfl_xor_sync(0xFFFFFFFFu, s, o);
        if (!lane) psall[pi] = s + bps[p] + bpf[p];
    }

    float acc[4][4];   // [i: a][j: p]
    #pragma unroll
    for (int i = 0; i < 4; i++)
        #pragma unroll
        for (int j = 0; j < 4; j++) acc[i][j] = 0.f;

    for (int cc = 0; cc < 8; cc++) {
        int c0 = cc * 64;
        __syncthreads();
        for (int i4 = tid; i4 < 1024; i4 += 256) {
            int p = i4 >> 4, q = i4 & 15;
            float4 v = *(const float4*)(wpf + (size_t)(p0 + p) * CC + c0 + q * 4);
            float* d = ubuf + p * SKPAD + q * 4;
            d[0] = v.x; d[1] = v.y; d[2] = v.z; d[3] = v.w;
        }
        __syncthreads();
        #pragma unroll
        for (int kk = 0; kk < 16; kk++) {
            int k = kg * 16 + kk;
            float wv[4], av[4];
            #pragma unroll
            for (int j = 0; j < 4; j++)
                wv[j] = ubuf[(pg + 16 * j) * SKPAD + k];
            #pragma unroll
            for (int i = 0; i < 4; i++)
                av[i] = aggs[(ag * 4 + i) * AGPAD + c0 + k];
            #pragma unroll
            for (int i = 0; i < 4; i++)
                #pragma unroll
                for (int j = 0; j < 4; j++)
                    acc[i][j] += av[i] * wv[j];
        }
    }
    __syncthreads();

    int tt = pg + 16 * ag;
    {
        float* d = ubuf + (kg * 64 + tt) * 17;
        #pragma unroll
        for (int i = 0; i < 4; i++)
            #pragma unroll
            for (int j = 0; j < 4; j++)
                d[i * 4 + j] = acc[i][j];
    }
    __syncthreads();

    if (kg == 0) {
        float contrib[4] = {0.f, 0.f, 0.f, 0.f};
        #pragma unroll
        for (int j = 0; j < 4; j++) {
            int pl = pg + 16 * j;
            float wt = wattS[pl], pb = psall[pl];
            #pragma unroll
            for (int i = 0; i < 4; i++) {
                float dot = 0.f;
                #pragma unroll
                for (int g = 0; g < 4; g++)
                    dot += ubuf[(g * 64 + tt) * 17 + i * 4 + j];
                contrib[i] += wt * tanhf(dot + pb);
            }
        }
        #pragma unroll
        for (int i = 0; i < 4; i++)
            scw[pg][ag * 4 + i] = contrib[i];
    }
    __syncthreads();
    if (tid < 16) {
        float v = 0.f;
        #pragma unroll
        for (int g = 0; g < 16; g++) v += scw[g][tid];
        g_scorep[blockIdx.y][b * 16 + tid] = v;
    }
}

// ---------------------------------------------------------------------------
// softmax (redundant per block) + weighted sums.  grid (64,5), block 256
__global__ void k_final(float* __restrict__ out) {
    __shared__ float sc[16];
    __shared__ float aw[16];
    int b = blockIdx.x, tid = threadIdx.x;
    if (tid < 16) {
        float v = 0.f;
        #pragma unroll
        for (int j = 0; j < 8; j++) v += g_scorep[j][b * 16 + tid];
        sc[tid] = v;
    }
    __syncthreads();
    if (tid < 16) {
        float m = -1e30f;
        #pragma unroll
        for (int i = 0; i < 16; i++) m = fmaxf(m, sc[i]);
        float sum = 0.f;
        #pragma unroll
        for (int i = 0; i < 16; i++) sum += expf(sc[i] - m);
        aw[tid] = expf(sc[tid] - m) / sum;
    }
    __syncthreads();

    int hw = blockIdx.y * 256 + tid;
    if (hw < HWW) {
        const float* X = out + OFF_X + (size_t)b * AA * HWW;
        float s = 0.f;
        #pragma unroll
        for (int a = 0; a < 16; a++) s += X[a * HWW + hw] * aw[a];
        out[OFF_AX + b * HWW + hw] = s;
        out[OFF_Z + b * 1201 + 1 + hw] = s;
    }
    if (tid == 0 && blockIdx.y == 0) {
        float z = 0.f;
        #pragma unroll
        for (int a = 0; a < 16; a++) z += g_y[b * 16 + a] * aw[a];
        out[OFF_Z + b * 1201] = z;
    }
}

// ---------------------------------------------------------------------------
extern "C" void kernel_launch(void* const* d_in, const int* in_sizes, int n_in,
                              void* d_out, int out_size) {
    const float* enc  = (const float*)d_in[0];
    const float* feat = (const float*)d_in[1];
    const float* subj = (const float*)d_in[2];
    const float* w2   = (const float*)d_in[3];
    const float* b2   = (const float*)d_in[4];
    const float* w3   = (const float*)d_in[5];
    const float* b3   = (const float*)d_in[6];
    const float* wd1  = (const float*)d_in[7];
    const float* bd1  = (const float*)d_in[8];
    const float* wd2  = (const float*)d_in[9];
    const float* bd2  = (const float*)d_in[10];
    const float* wpf  = (const float*)d_in[11];
    const float* bpf  = (const float*)d_in[12];
    const float* wps  = (const float*)d_in[13];
    const float* bps  = (const float*)d_in[14];
    const float* watt = (const float*)d_in[15];
    float* out = (float*)d_out;

    cudaEventRecord(g_evFork, 0);
    cudaStreamWaitEvent(g_s1, g_evFork, 0);

    k_xp<<<dim3(64, 10, 2), 128>>>(feat, w3);                      // 1 (s0)
    cudaEventRecord(g_evXp, 0);
    k_aggr<<<dim3(64, NZ), 256>>>(enc, b3);                        // 2 (s0)
    k_sumaggr<<<512, 256>>>();                                     // 3 (s0)
    k_score<<<dim3(64, 8), 256>>>(subj, wps, bps, wpf, bpf, watt); // 4 (s0) <- profiled

    k_drt1f<<<dim3(64, 8), 384, 0, g_s1>>>(feat, wd1);             // 5 (s1)
    k_ydrt2<<<64, 512, 0, g_s1>>>(w2, b2, wd2, bd2, bd1, out);     // 6 (s1)
    cudaStreamWaitEvent(g_s1, g_evXp, 0);
    k_xcomb<<<4800, 256, 0, g_s1>>>(b3, out);                      // 7 (s1)

    cudaEventRecord(g_evJoin, g_s1);
    cudaStreamWaitEvent(0, g_evJoin, 0);
    k_final<<<dim3(64, 5), 256>>>(out);                            // 8 (s0)
}